// round 3
// baseline (speedup 1.0000x reference)
#include <cuda_runtime.h>
#include <math.h>

// Problem constants
#define B 256
#define N 256
#define D 512
#define EPSV 1e-8f

#define DSPLIT 4
#define DCHUNK (D / DSPLIT)   // 128 d's per block
#define DC4 (DCHUNK / 4)      // 32 float4 columns per block
#define NGROUPS 8
#define NCHUNK (N / NGROUPS)  // 32 n-rows per thread-group
// block = DC4 * NGROUPS = 256 threads

// Scratch for delta (allocation-free rule -> __device__ global)
__device__ float g_delta[B * D];

// Fused kernel: pass 1 reduces |pd| over n for a (b, d-chunk) slice (128 KB,
// streamed from DRAM into L2), computes lam/beta/delta, writes new_central/
// new_err; pass 2 re-reads the slice (L2 hit) and writes scaled_pd with
// evict-first stores so the write stream doesn't evict the pd slices.
__global__ __launch_bounds__(256, 4) void k_fused(const float* __restrict__ cv,
                                                  const float4* __restrict__ pd4,
                                                  const float* __restrict__ err,
                                                  float* __restrict__ out_central,
                                                  float4* __restrict__ out_pd4,
                                                  float* __restrict__ out_err) {
    const int b = blockIdx.x;
    const int h = blockIdx.y;  // d-chunk index
    const int tid = threadIdx.x;
    const int d4 = tid & (DC4 - 1);  // 0..31 (float4 column within chunk)
    const int g = tid >> 5;          // 0..7  (n-group)

    __shared__ float4 s_acc[NGROUPS][DC4];
    __shared__ float4 s_lam[DC4];

    // Base pointer for this thread's float4 column
    const float4* p = pd4 + (size_t)b * N * (D / 4) + (size_t)(g * NCHUNK) * (D / 4)
                      + h * DC4 + d4;

    // Pass 1: abs-sum over this group's 32 n-rows
    float4 acc = make_float4(0.f, 0.f, 0.f, 0.f);
#pragma unroll 8
    for (int n = 0; n < NCHUNK; n++) {
        const float4 v = p[(size_t)n * (D / 4)];
        acc.x += fabsf(v.x);
        acc.y += fabsf(v.y);
        acc.z += fabsf(v.z);
        acc.w += fabsf(v.w);
    }
    s_acc[g][d4] = acc;
    __syncthreads();

    // Combine groups + compute lam/beta/delta: threads 0..127, one d each
    if (tid < DCHUNK) {
        const int dc4 = tid >> 2;
        const int lane = tid & 3;
        float r = 0.f;
#pragma unroll
        for (int gg = 0; gg < NGROUPS; gg++)
            r += ((const float*)&s_acc[gg][dc4])[lane];

        const int bd = b * D + h * DCHUNK + tid;
        const float e = err[bd];
        const float c = cv[bd];

        const float radius = r + fabsf(e);
        const float lower = c - radius;
        const float upper = c + radius;
        const float rl = fmaxf(lower, 0.f);
        const float ru = fmaxf(upper, 0.f);

        float lam = (ru - rl) / (upper - lower + EPSV);
        if (lower >= 0.f) lam = 1.f;
        if (upper < 0.f) lam = 0.f;
        if (isnan(lam)) lam = 0.f;
        lam = fminf(fmaxf(lam, 0.f), 1.f);

        const float beta = (rl - lam * lower) * 0.5f;

        g_delta[bd] = fabsf(beta);
        out_central[bd] = lam * c + beta;
        out_err[bd] = lam * e;
        ((float*)&s_lam[dc4])[lane] = lam;
    }
    __syncthreads();

    // Pass 2: re-read slice (L2 hit) and write scaled_pd (evict-first).
    // new_pd layout: (B, N+D, D); rows [0, N) are scaled_pd.
    const float4 lam4 = s_lam[d4];
    float4* o = out_pd4 + (size_t)b * ((N + D) * (D / 4)) + (size_t)(g * NCHUNK) * (D / 4)
                + h * DC4 + d4;
#pragma unroll 8
    for (int n = 0; n < NCHUNK; n++) {
        const float4 v = p[(size_t)n * (D / 4)];
        float4 w;
        w.x = v.x * lam4.x;
        w.y = v.y * lam4.y;
        w.z = v.z * lam4.z;
        w.w = v.w * lam4.w;
        __stcs(&o[(size_t)n * (D / 4)], w);
    }
}

// Diag-embed region: out[b, N+r, d] = (r==d) ? delta[b][r] : 0.
// Pure write kernel, 268 MB. Each thread writes 8 contiguous float4 (128 B)
// of zeros; if the diagonal element falls in its 32-float span, it is patched
// with a follow-up scalar store (same-thread same-address => program order).
#define SEGS 16  // 32-float segments per 512-float row
__global__ __launch_bounds__(256) void k_diag(float4* __restrict__ out_pd4) {
    const unsigned idx = blockIdx.x * blockDim.x + threadIdx.x;  // < B*D*SEGS
    const unsigned seg = idx & (SEGS - 1);   // segment within row
    const unsigned row = idx >> 4;           // global row in [0, B*D)
    const unsigned b = row >> 9;             // / D
    const unsigned r = row & (D - 1);

    float4* ptr = out_pd4 + (size_t)b * ((N + D) * (D / 4)) + N * (D / 4)
                  + (size_t)r * (D / 4) + seg * 8;

    const float4 z = make_float4(0.f, 0.f, 0.f, 0.f);
#pragma unroll
    for (int j = 0; j < 8; j++) {
        __stcs(&ptr[j], z);
    }

    const unsigned d0 = seg << 5;  // first float index of this segment
    if (r - d0 < 32u) {            // diagonal element in this span
        __stcs((float*)ptr + (r - d0), g_delta[b * D + r]);
    }
}

extern "C" void kernel_launch(void* const* d_in, const int* in_sizes, int n_in,
                              void* d_out, int out_size) {
    const float* cv = (const float*)d_in[0];   // (256, 512)
    const float* pd = (const float*)d_in[1];   // (256, 256, 512)
    const float* err = (const float*)d_in[2];  // (256, 512)

    float* out = (float*)d_out;
    // Output layout: [new_central (B*D)] [new_pd (B*(N+D)*D)] [new_err (B*D)]
    float* out_central = out;
    float* out_pd = out + (size_t)B * D;
    float* out_err = out + (size_t)B * D + (size_t)B * (N + D) * D;

    // Fused stats + scale
    {
        dim3 grid(B, DSPLIT);
        k_fused<<<grid, 256>>>(cv, (const float4*)pd, err,
                               out_central, (float4*)out_pd, out_err);
    }

    // Diag region: B*D rows, 16 segment-threads per row
    {
        const unsigned total = B * D * SEGS;  // 2,097,152 threads
        k_diag<<<total / 256, 256>>>((float4*)out_pd);
    }
}

// round 4
// speedup vs baseline: 1.4769x; 1.4769x over previous
#include <cuda_runtime.h>
#include <math.h>

// Problem constants
#define B 256
#define N 256
#define D 512
#define EPSV 1e-8f

#define DSPLIT 4
#define DCHUNK (D / DSPLIT)   // 128 d's per block
#define DC4 (DCHUNK / 4)      // 32 float4 columns per block
#define NGROUPS 8
#define NCHUNK (N / NGROUPS)  // 32 n-rows per thread-group
// block = DC4 * NGROUPS = 256 threads

// Scratch for delta (allocation-free rule -> __device__ global)
__device__ float g_delta[B * D];

// Fused kernel (R2 version, plain stores): pass 1 reduces |pd| over n for a
// (b, d-chunk) slice (128 KB, streamed from DRAM into L2), computes
// lam/beta/delta, writes new_central/new_err; pass 2 re-reads the slice
// (L2 hit) and writes scaled_pd.
__global__ __launch_bounds__(256, 4) void k_fused(const float* __restrict__ cv,
                                                  const float4* __restrict__ pd4,
                                                  const float* __restrict__ err,
                                                  float* __restrict__ out_central,
                                                  float4* __restrict__ out_pd4,
                                                  float* __restrict__ out_err) {
    const int b = blockIdx.x;
    const int h = blockIdx.y;  // d-chunk index
    const int tid = threadIdx.x;
    const int d4 = tid & (DC4 - 1);  // 0..31 (float4 column within chunk)
    const int g = tid >> 5;          // 0..7  (n-group)

    __shared__ float4 s_acc[NGROUPS][DC4];
    __shared__ float4 s_lam[DC4];

    // Base pointer for this thread's float4 column
    const float4* p = pd4 + (size_t)b * N * (D / 4) + (size_t)(g * NCHUNK) * (D / 4)
                      + h * DC4 + d4;

    // Pass 1: abs-sum over this group's 32 n-rows
    float4 acc = make_float4(0.f, 0.f, 0.f, 0.f);
#pragma unroll 8
    for (int n = 0; n < NCHUNK; n++) {
        const float4 v = p[(size_t)n * (D / 4)];
        acc.x += fabsf(v.x);
        acc.y += fabsf(v.y);
        acc.z += fabsf(v.z);
        acc.w += fabsf(v.w);
    }
    s_acc[g][d4] = acc;
    __syncthreads();

    // Combine groups + compute lam/beta/delta: threads 0..127, one d each
    if (tid < DCHUNK) {
        const int dc4 = tid >> 2;
        const int lane = tid & 3;
        float r = 0.f;
#pragma unroll
        for (int gg = 0; gg < NGROUPS; gg++)
            r += ((const float*)&s_acc[gg][dc4])[lane];

        const int bd = b * D + h * DCHUNK + tid;
        const float e = err[bd];
        const float c = cv[bd];

        const float radius = r + fabsf(e);
        const float lower = c - radius;
        const float upper = c + radius;
        const float rl = fmaxf(lower, 0.f);
        const float ru = fmaxf(upper, 0.f);

        float lam = (ru - rl) / (upper - lower + EPSV);
        if (lower >= 0.f) lam = 1.f;
        if (upper < 0.f) lam = 0.f;
        if (isnan(lam)) lam = 0.f;
        lam = fminf(fmaxf(lam, 0.f), 1.f);

        const float beta = (rl - lam * lower) * 0.5f;

        g_delta[bd] = fabsf(beta);
        out_central[bd] = lam * c + beta;
        out_err[bd] = lam * e;
        ((float*)&s_lam[dc4])[lane] = lam;
    }
    __syncthreads();

    // Pass 2: re-read slice (L2 hit) and write scaled_pd.
    // new_pd layout: (B, N+D, D); rows [0, N) are scaled_pd.
    const float4 lam4 = s_lam[d4];
    float4* o = out_pd4 + (size_t)b * ((N + D) * (D / 4)) + (size_t)(g * NCHUNK) * (D / 4)
                + h * DC4 + d4;
#pragma unroll 8
    for (int n = 0; n < NCHUNK; n++) {
        const float4 v = p[(size_t)n * (D / 4)];
        float4 w;
        w.x = v.x * lam4.x;
        w.y = v.y * lam4.y;
        w.z = v.z * lam4.z;
        w.w = v.w * lam4.w;
        o[(size_t)n * (D / 4)] = w;
    }
}

// Diag-embed region: out[b, N+r, d] = (r==d) ? delta[b][r] : 0.
// One WARP per row (128 float4): each lane writes 4 float4 at lane + 32*j,
// so every warp store is 512 B contiguous (fully coalesced). The diagonal
// element is folded into the stored value with a branch-free select.
__global__ __launch_bounds__(256) void k_diag(float4* __restrict__ out_pd4) {
    const unsigned wid = (blockIdx.x * blockDim.x + threadIdx.x) >> 5;  // row id, < B*D
    const unsigned lane = threadIdx.x & 31;
    const unsigned b = wid >> 9;        // / D
    const unsigned r = wid & (D - 1);

    float4* row = out_pd4 + (size_t)b * ((N + D) * (D / 4)) + N * (D / 4)
                  + (size_t)r * (D / 4);

    const unsigned diag4 = r >> 2;  // float4 index holding the diagonal
    float4 dv = make_float4(0.f, 0.f, 0.f, 0.f);
    ((float*)&dv)[r & 3] = g_delta[b * D + r];  // broadcast load
    const float4 z = make_float4(0.f, 0.f, 0.f, 0.f);

#pragma unroll
    for (unsigned j = 0; j < 4; j++) {
        const unsigned c = j * 32 + lane;
        row[c] = (c == diag4) ? dv : z;
    }
}

extern "C" void kernel_launch(void* const* d_in, const int* in_sizes, int n_in,
                              void* d_out, int out_size) {
    const float* cv = (const float*)d_in[0];   // (256, 512)
    const float* pd = (const float*)d_in[1];   // (256, 256, 512)
    const float* err = (const float*)d_in[2];  // (256, 512)

    float* out = (float*)d_out;
    // Output layout: [new_central (B*D)] [new_pd (B*(N+D)*D)] [new_err (B*D)]
    float* out_central = out;
    float* out_pd = out + (size_t)B * D;
    float* out_err = out + (size_t)B * D + (size_t)B * (N + D) * D;

    // Fused stats + scale
    {
        dim3 grid(B, DSPLIT);
        k_fused<<<grid, 256>>>(cv, (const float4*)pd, err,
                               out_central, (float4*)out_pd, out_err);
    }

    // Diag region: one warp per row, B*D rows -> B*D*32 threads
    {
        const unsigned total = B * D * 32;  // 4,194,304 threads
        k_diag<<<total / 256, 256>>>((float4*)out_pd);
    }
}